// round 16
// baseline (speedup 1.0000x reference)
#include <cuda_runtime.h>
#include <math.h>

// Problem constants (fixed by the reference setup)
#define N_USER 60000
#define N_ITEM 40000
#define NN     (N_USER + N_ITEM)   // 100000 nodes
#define D      64
#define EMAX   800000
#define EHALF  (EMAX / 2)
#define NB_SCAN ((NN + 1023) / 1024)   // 98 blocks
#define INIT_BLKS ((NN + 7) / 8)       // 12500 (8 warps/block, warp per row)
#define HIST_BLKS 1024

// ---- static device scratch (no allocations allowed) ----
__device__ float  g_embA[NN * D];   // emb0 -> overwritten by emb2 (layer-1 output)
__device__ float  g_embB[NN * D];   // emb1 (layer-0 output), preserved
__device__ float  g_rnorm[NN];      // reciprocal norms
__device__ float  g_rowsum[NN];     // USER reciprocal L1 rowsums (items unused)
__device__ float  g_rowacc[3 * N_ITEM]; // per-layer item rowsum accumulators (atomic)
__device__ float4 g_edge[EMAX];     // {col(bits), cos, mem, aval}
__device__ int2   g_cr[EHALF];      // user-side CSR slots: {col, reverse slot}
__device__ int    g_off[EMAX];      // per-edge within-row offset (from hist atomics)
__device__ int    g_rowptr[NN + 1];
__device__ int    g_deg[NN];
__device__ int    g_bsum[128];
__device__ float  g_U[2048 * D];    // 0.25*(emb0+..+emb3) at sampled user rows
__device__ float  g_I[2048 * D];    // same for items

// reciprocal of a layer's item rowsum (reference: divide iff rowsum>0 else by 1)
__device__ __forceinline__ float item_rinv(int layer, int item) {
    float rs = g_rowacc[layer * N_ITEM + item];
    return (rs > 0.f) ? 1.f / rs : 1.f;
}

// ---------------- fused: degree histogram (+offset capture) + emb init + rnorm0 ----

__global__ __launch_bounds__(256) void k_hist_init(const int* __restrict__ src, int E,
                                                   const float* __restrict__ ue,
                                                   const float* __restrict__ ie) {
    if (blockIdx.x < INIT_BLKS) {
        int row = blockIdx.x * 8 + (threadIdx.x >> 5);
        if (row >= NN) return;
        int lane = threadIdx.x & 31;
        const float* srcp = (row < N_USER) ? (ue + row * D) : (ie + (row - N_USER) * D);
        float2 v = *(const float2*)(srcp + lane * 2);
        *(float2*)(g_embA + row * D + lane * 2) = v;
        float s = v.x * v.x + v.y * v.y;
        #pragma unroll
        for (int o = 16; o; o >>= 1) s += __shfl_xor_sync(0xffffffffu, s, o);
        if (lane == 0) g_rnorm[row] = (s > 1e-24f) ? rsqrtf(s) : 0.f;
    } else {
        // histogram that also records each edge's within-row slot offset
        int base = (blockIdx.x - INIT_BLKS) * 256 + threadIdx.x;
        for (int e = base; e < E; e += HIST_BLKS * 256)
            g_off[e] = atomicAdd(&g_deg[src[e]], 1);
    }
}

// ---------------- CSR build ----------------

__global__ void k_scanA() {
    __shared__ int wsum[32];
    int i = blockIdx.x * 1024 + threadIdx.x;
    int lane = threadIdx.x & 31, wid = threadIdx.x >> 5;
    int v = (i < NN) ? g_deg[i] : 0;
    int x = v;
    #pragma unroll
    for (int o = 1; o < 32; o <<= 1) {
        int y = __shfl_up_sync(0xffffffffu, x, o);
        if (lane >= o) x += y;
    }
    if (lane == 31) wsum[wid] = x;
    __syncthreads();
    if (wid == 0) {
        int s = wsum[lane];
        #pragma unroll
        for (int o = 1; o < 32; o <<= 1) {
            int y = __shfl_up_sync(0xffffffffu, s, o);
            if (lane >= o) s += y;
        }
        wsum[lane] = s;
    }
    __syncthreads();
    int woff = (wid > 0) ? wsum[wid - 1] : 0;
    int incl = x + woff;
    if (i < NN) g_rowptr[i] = incl - v;  // exclusive, local to block
    if (threadIdx.x == 1023) g_bsum[blockIdx.x] = incl;
}

// adds cross-block offsets
__global__ void k_scanC(int E) {
    __shared__ int ssum[128];
    int t = threadIdx.x;
    if (t < 128) ssum[t] = (t < blockIdx.x) ? g_bsum[t] : 0;
    __syncthreads();
    if (t < 64) ssum[t] += ssum[t + 64];
    __syncthreads();
    if (t < 32) {
        int s = ssum[t] + ssum[t + 32];
        #pragma unroll
        for (int o = 16; o; o >>= 1) s += __shfl_down_sync(0xffffffffu, s, o);
        if (t == 0) ssum[0] = s;
    }
    __syncthreads();
    int off = ssum[0];
    int i = blockIdx.x * 1024 + t;
    if (i < NN) g_rowptr[i] += off;
    if (i == 0) g_rowptr[NN] = E;
}

// atomic-free scatter: slot = rowptr[node] + precomputed offset
__global__ __launch_bounds__(1024) void k_scatter(const int* __restrict__ src,
                                                  const float* __restrict__ adj,
                                                  int EH) {
    int e = blockIdx.x * 1024 + threadIdx.x;
    if (e >= EH) return;
    int u  = src[e];
    int iv = src[e + EH];
    float a = adj[e];
    int pos1 = g_rowptr[u]  + g_off[e];
    int pos2 = g_rowptr[iv] + g_off[e + EH];
    g_edge[pos1] = make_float4(__int_as_float(iv), 0.f, a, a);
    g_edge[pos2] = make_float4(__int_as_float(u), 0.f, a, a);
    g_cr[pos1]   = make_int2(iv, pos2);   // user rows occupy slots [0, EH)
}

// ---------------- per-layer edge passes (verified bodies) ----------------
// k_cos: USER rows only (cos symmetric; scatter to reverse slot too).
// Item rowsums accumulate via spread atomics into the layer's accumulator slice.

__global__ __launch_bounds__(256) void k_cos(int cur, int layer) {
    const float* __restrict__ emb = cur ? g_embB : g_embA;
    int row = blockIdx.x * 8 + (threadIdx.x >> 5);
    if (row >= N_USER) return;
    int lane = threadIdx.x & 31;
    int g = lane >> 3, sl = lane & 7;

    const float* rp = emb + row * D + sl * 4;
    float4 e0 = *(const float4*)(rp);
    float4 e1 = *(const float4*)(rp + 32);
    float rn_r = g_rnorm[row];

    int beg = g_rowptr[row], end = g_rowptr[row + 1];
    int nit = (end - beg + 3) >> 2;

    int pos = beg + g;
    bool actn = pos < end;
    int2 crn = actn ? g_cr[pos] : make_int2(0, 0);

    float* acc = g_rowacc + layer * N_ITEM;

    float rs = 0.f;
    for (int it = 0; it < nit; it++) {
        bool act = actn;
        int2 cr = crn;
        int curpos = pos;
        pos += 4;
        actn = pos < end;
        if (actn) crn = g_cr[pos];

        float p = 0.f;
        float rn_c = 0.f;
        if (act) {
            const float* cp = emb + cr.x * D + sl * 4;
            float4 d0 = *(const float4*)(cp);
            float4 d1 = *(const float4*)(cp + 32);
            rn_c = g_rnorm[cr.x];
            p = e0.x * d0.x + e0.y * d0.y + e0.z * d0.z + e0.w * d0.w
              + e1.x * d1.x + e1.y * d1.y + e1.z * d1.z + e1.w * d1.w;
        }
        p += __shfl_xor_sync(0xffffffffu, p, 1);
        p += __shfl_xor_sync(0xffffffffu, p, 2);
        p += __shfl_xor_sync(0xffffffffu, p, 4);
        float cs = p * rn_r * rn_c;
        if (act && sl == 0) {
            ((float*)(g_edge + curpos))[1] = cs;   // user-side slot
            ((float*)(g_edge + cr.y))[1]   = cs;   // item-side (reverse) slot
            atomicAdd(&acc[cr.x - N_USER], fabsf(cs));  // item L1 rowsum
        }
        rs += fabsf(cs);
    }
    rs += __shfl_xor_sync(0xffffffffu, rs, 8);
    rs += __shfl_xor_sync(0xffffffffu, rs, 16);
    if (lane == 0) g_rowsum[row] = (rs > 0.f) ? 1.f / rs : 1.f;
}

// layers 0,1 only: coef -> prune -> mem EMA -> SpMM row accumulate (+ next rnorm)
__global__ __launch_bounds__(256) void k_spmm(int cur, int layer,
                                              const float* __restrict__ W,
                                              const float* __restrict__ B) {
    const float* __restrict__ embin = cur ? g_embB : g_embA;
    float* embout                   = cur ? g_embA : g_embB;
    int row = blockIdx.x * 8 + (threadIdx.x >> 5);
    if (row >= NN) return;
    int lane = threadIdx.x & 31;
    int g = lane >> 3, sl = lane & 7;

    bool rowIsUser = row < N_USER;
    float w0 = W[0], w1 = W[1], bb = B[0];
    float invr = rowIsUser ? g_rowsum[row] : item_rinv(layer, row - N_USER);
    int beg = g_rowptr[row], end = g_rowptr[row + 1];
    int nit = (end - beg + 3) >> 2;

    int pos = beg + g;
    bool actn = pos < end;
    float4 en = actn ? g_edge[pos] : make_float4(0, 0, 0, 0);

    float a0 = 0.f, a1 = 0.f, a2 = 0.f, a3 = 0.f;
    float a4 = 0.f, a5 = 0.f, a6 = 0.f, a7 = 0.f;
    for (int it = 0; it < nit; it++) {
        bool act = actn;
        float4 er = en;
        int curpos = pos;
        pos += 4;
        actn = pos < end;
        if (actn) en = g_edge[pos];

        if (act) {
            int c = __float_as_int(er.x);
            float cs = er.y;
            float c1 = cs * invr;
            // cos symmetric: coef[rev] = cs / rowsum[neighbor]
            float rc = rowIsUser ? item_rinv(layer, c - N_USER) : g_rowsum[c];
            float c2 = cs * rc;
            float z = w0 * c1 + w1 * c2 + bb;      // sigmoid(z)>0.5 <=> z>0
            float coef = (z > 0.f) ? c1 : 0.f;
            float m = 0.5f * (er.z + coef);
            if (sl == 0) ((float*)(g_edge + curpos))[2] = m;
            float gv = m * er.w;
            const float* cp = embin + c * D + sl * 4;
            float4 d0 = *(const float4*)(cp);
            float4 d1 = *(const float4*)(cp + 32);
            a0 += gv * d0.x; a1 += gv * d0.y; a2 += gv * d0.z; a3 += gv * d0.w;
            a4 += gv * d1.x; a5 += gv * d1.y; a6 += gv * d1.z; a7 += gv * d1.w;
        }
    }
    #pragma unroll
    for (int o = 8; o <= 16; o <<= 1) {
        a0 += __shfl_xor_sync(0xffffffffu, a0, o);
        a1 += __shfl_xor_sync(0xffffffffu, a1, o);
        a2 += __shfl_xor_sync(0xffffffffu, a2, o);
        a3 += __shfl_xor_sync(0xffffffffu, a3, o);
        a4 += __shfl_xor_sync(0xffffffffu, a4, o);
        a5 += __shfl_xor_sync(0xffffffffu, a5, o);
        a6 += __shfl_xor_sync(0xffffffffu, a6, o);
        a7 += __shfl_xor_sync(0xffffffffu, a7, o);
    }
    float ss = a0 * a0 + a1 * a1 + a2 * a2 + a3 * a3
             + a4 * a4 + a5 * a5 + a6 * a6 + a7 * a7;
    ss += __shfl_xor_sync(0xffffffffu, ss, 1);
    ss += __shfl_xor_sync(0xffffffffu, ss, 2);
    ss += __shfl_xor_sync(0xffffffffu, ss, 4);
    if (g == 0) {
        float* op = embout + row * D + sl * 4;
        *(float4*)(op)      = make_float4(a0, a1, a2, a3);
        *(float4*)(op + 32) = make_float4(a4, a5, a6, a7);
        if (sl == 0) g_rnorm[row] = (ss > 1e-24f) ? rsqrtf(ss) : 0.f;
    }
}

// layer-2 SpMM restricted to the SAMPLED rows only, fused with the light mean
__global__ __launch_bounds__(256) void k_final(const int* __restrict__ users,
                                               const int* __restrict__ items,
                                               const float* __restrict__ ue,
                                               const float* __restrict__ ie,
                                               const float* __restrict__ W,
                                               const float* __restrict__ B,
                                               int Bu, int Bi) {
    int idx = blockIdx.x * 8 + (threadIdx.x >> 5);   // sample index
    if (idx >= Bu + Bi) return;
    int lane = threadIdx.x & 31;
    int g = lane >> 3, sl = lane & 7;

    bool isU = idx < Bu;
    int row = isU ? users[idx] : (N_USER + items[idx - Bu]);
    float* outp = isU ? (g_U + idx * D) : (g_I + (idx - Bu) * D);
    const float* e0p = isU ? (ue + row * D) : (ie + (row - N_USER) * D);

    const float* __restrict__ embin = g_embA;   // emb2 (layer-1 output)

    float w0 = W[0], w1 = W[1], bb = B[0];
    float invr = isU ? g_rowsum[row] : item_rinv(2, row - N_USER);
    int beg = g_rowptr[row], end = g_rowptr[row + 1];
    int nit = (end - beg + 3) >> 2;

    int pos = beg + g;
    bool actn = pos < end;
    float4 en = actn ? g_edge[pos] : make_float4(0, 0, 0, 0);

    float a0 = 0.f, a1 = 0.f, a2 = 0.f, a3 = 0.f;
    float a4 = 0.f, a5 = 0.f, a6 = 0.f, a7 = 0.f;
    for (int it = 0; it < nit; it++) {
        bool act = actn;
        float4 er = en;
        pos += 4;
        actn = pos < end;
        if (actn) en = g_edge[pos];

        if (act) {
            int c = __float_as_int(er.x);
            float cs = er.y;
            float c1 = cs * invr;
            float rc = isU ? item_rinv(2, c - N_USER) : g_rowsum[c];
            float c2 = cs * rc;
            float z = w0 * c1 + w1 * c2 + bb;
            float coef = (z > 0.f) ? c1 : 0.f;
            float m = 0.5f * (er.z + coef);      // no mem writeback (last layer)
            float gv = m * er.w;
            const float* cp = embin + c * D + sl * 4;
            float4 d0 = *(const float4*)(cp);
            float4 d1 = *(const float4*)(cp + 32);
            a0 += gv * d0.x; a1 += gv * d0.y; a2 += gv * d0.z; a3 += gv * d0.w;
            a4 += gv * d1.x; a5 += gv * d1.y; a6 += gv * d1.z; a7 += gv * d1.w;
        }
    }
    #pragma unroll
    for (int o = 8; o <= 16; o <<= 1) {
        a0 += __shfl_xor_sync(0xffffffffu, a0, o);
        a1 += __shfl_xor_sync(0xffffffffu, a1, o);
        a2 += __shfl_xor_sync(0xffffffffu, a2, o);
        a3 += __shfl_xor_sync(0xffffffffu, a3, o);
        a4 += __shfl_xor_sync(0xffffffffu, a4, o);
        a5 += __shfl_xor_sync(0xffffffffu, a5, o);
        a6 += __shfl_xor_sync(0xffffffffu, a6, o);
        a7 += __shfl_xor_sync(0xffffffffu, a7, o);
    }
    if (g == 0) {
        float4 z0 = *(const float4*)(e0p + sl * 4);           // emb0 (inputs)
        float4 z1 = *(const float4*)(e0p + sl * 4 + 32);
        const float* b1 = g_embB + row * D + sl * 4;          // emb1
        float4 y0 = *(const float4*)(b1);
        float4 y1 = *(const float4*)(b1 + 32);
        const float* b2 = g_embA + row * D + sl * 4;          // emb2
        float4 x0 = *(const float4*)(b2);
        float4 x1 = *(const float4*)(b2 + 32);
        float4 r0 = make_float4(0.25f * (z0.x + y0.x + x0.x + a0),
                                0.25f * (z0.y + y0.y + x0.y + a1),
                                0.25f * (z0.z + y0.z + x0.z + a2),
                                0.25f * (z0.w + y0.w + x0.w + a3));
        float4 r1 = make_float4(0.25f * (z1.x + y1.x + x1.x + a4),
                                0.25f * (z1.y + y1.y + x1.y + a5),
                                0.25f * (z1.z + y1.z + x1.z + a6),
                                0.25f * (z1.w + y1.w + x1.w + a7));
        *(float4*)(outp + sl * 4)      = r0;
        *(float4*)(outp + sl * 4 + 32) = r1;
    }
}

// ---------------- final sigmoid GEMM (verified R13 version; FMA-bound) ----------

__global__ void k_gemm(float* __restrict__ out, int Bu, int Bi) {
    __shared__ float As[64][65];
    __shared__ float Bs[64][65];
    int tx = threadIdx.x, ty = threadIdx.y;       // 16x16
    int t = ty * 16 + tx;
    int rowBase = blockIdx.y * 64, colBase = blockIdx.x * 64;
    #pragma unroll
    for (int i = 0; i < 4; i++) {
        int j = t + i * 256;       // float4 slot 0..1023
        int r = j >> 4;
        int kq = (j & 15) * 4;
        float4 a = (rowBase + r < Bu) ? *(const float4*)(g_U + (rowBase + r) * 64 + kq)
                                      : make_float4(0, 0, 0, 0);
        As[r][kq] = a.x; As[r][kq + 1] = a.y; As[r][kq + 2] = a.z; As[r][kq + 3] = a.w;
        float4 b = (colBase + r < Bi) ? *(const float4*)(g_I + (colBase + r) * 64 + kq)
                                      : make_float4(0, 0, 0, 0);
        Bs[r][kq] = b.x; Bs[r][kq + 1] = b.y; Bs[r][kq + 2] = b.z; Bs[r][kq + 3] = b.w;
    }
    __syncthreads();
    float acc[4][4] = {};
    #pragma unroll
    for (int k = 0; k < 64; k++) {
        float a0 = As[ty * 4 + 0][k], a1 = As[ty * 4 + 1][k];
        float a2 = As[ty * 4 + 2][k], a3 = As[ty * 4 + 3][k];
        float b0 = Bs[tx * 4 + 0][k], b1 = Bs[tx * 4 + 1][k];
        float b2 = Bs[tx * 4 + 2][k], b3 = Bs[tx * 4 + 3][k];
        acc[0][0] += a0 * b0; acc[0][1] += a0 * b1; acc[0][2] += a0 * b2; acc[0][3] += a0 * b3;
        acc[1][0] += a1 * b0; acc[1][1] += a1 * b1; acc[1][2] += a1 * b2; acc[1][3] += a1 * b3;
        acc[2][0] += a2 * b0; acc[2][1] += a2 * b1; acc[2][2] += a2 * b2; acc[2][3] += a2 * b3;
        acc[3][0] += a3 * b0; acc[3][1] += a3 * b1; acc[3][2] += a3 * b2; acc[3][3] += a3 * b3;
    }
    #pragma unroll
    for (int i = 0; i < 4; i++)
        #pragma unroll
        for (int j = 0; j < 4; j++) {
            int r = rowBase + ty * 4 + i;
            int c = colBase + tx * 4 + j;
            if (r < Bu && c < Bi)
                out[r * Bi + c] = 1.f / (1.f + __expf(-acc[i][j]));
        }
}

// ---------------- launch ----------------

extern "C" void kernel_launch(void* const* d_in, const int* in_sizes, int n_in,
                              void* d_out, int out_size) {
    const int*   users    = (const int*)d_in[0];
    const int*   items    = (const int*)d_in[1];
    const float* user_emb = (const float*)d_in[2];
    const float* item_emb = (const float*)d_in[3];
    const float* W_prune  = (const float*)d_in[4];
    const float* b_prune  = (const float*)d_in[5];
    const int*   src      = (const int*)d_in[6];
    // d_in[7] = dst (mirrors src), d_in[8] = rev_perm (unused)
    const float* adj_vals = (const float*)d_in[9];

    int Bu = in_sizes[0];
    int Bi = in_sizes[1];
    int E  = in_sizes[6];
    int EH = E / 2;

    float* out = (float*)d_out;

    // zero degree counters + all 3 layers' item rowsum accumulators
    void* degp = nullptr;
    cudaGetSymbolAddress(&degp, g_deg);
    cudaMemsetAsync(degp, 0, NN * sizeof(int));
    void* accp = nullptr;
    cudaGetSymbolAddress(&accp, g_rowacc);
    cudaMemsetAsync(accp, 0, 3 * N_ITEM * sizeof(float));

    // fused: degree histogram (capturing per-edge offsets) + emb init + rnorm0
    k_hist_init<<<INIT_BLKS + HIST_BLKS, 256>>>(src, E, user_emb, item_emb);

    // CSR build; scatter is atomic-free (rowptr + captured offset)
    k_scanA<<<NB_SCAN, 1024>>>();
    k_scanC<<<NB_SCAN, 1024>>>(E);
    k_scatter<<<(EH + 1023) / 1024, 1024>>>(src, adj_vals, EH);

    // layers 0,1: full passes (no rsinv pass — reciprocals computed on the fly)
    int ublocks = (N_USER + 7) / 8;
    int ablocks = (NN + 7) / 8;
    for (int l = 0; l < 2; l++) {
        k_cos<<<ublocks, 256>>>(l & 1, l);
        k_spmm<<<ablocks, 256>>>(l & 1, l, W_prune, b_prune);
    }
    // layer 2: full cos, then SpMM only at the 4096 sampled rows
    k_cos<<<ublocks, 256>>>(0, 2);       // emb2 in g_embA
    int fblocks = (Bu + Bi + 7) / 8;
    k_final<<<fblocks, 256>>>(users, items, user_emb, item_emb,
                              W_prune, b_prune, Bu, Bi);

    // sigmoid GEMM on the pre-scaled sampled embeddings
    dim3 gblk(16, 16);
    dim3 ggrd((Bi + 63) / 64, (Bu + 63) / 64);
    k_gemm<<<ggrd, gblk>>>(out, Bu, Bi);
}

// round 17
// speedup vs baseline: 1.0776x; 1.0776x over previous
#include <cuda_runtime.h>
#include <math.h>

// Problem constants (fixed by the reference setup)
#define N_USER 60000
#define N_ITEM 40000
#define NN     (N_USER + N_ITEM)   // 100000 nodes
#define D      64
#define EMAX   800000
#define EHALF  (EMAX / 2)
#define NB_SCAN ((NN + 1023) / 1024)   // 98 blocks (all wave-1 resident)
#define INIT_BLKS ((NN + 7) / 8)       // 12500 (8 warps/block, warp per row)
#define HIST_BLKS 1024

// ---- static device scratch (no allocations allowed) ----
__device__ float  g_embA[NN * D];   // emb0 -> overwritten by emb2 (layer-1 output)
__device__ float  g_embB[NN * D];   // emb1 (layer-0 output), preserved
__device__ float  g_rnorm[NN];      // reciprocal norms
__device__ float  g_rowsum[NN];     // reciprocal L1 rowsums (1 if rowsum<=0)
__device__ float  g_rowacc[N_ITEM]; // item rowsum accumulators (atomic)
__device__ float4 g_edge[EMAX];     // {col(bits), cos, mem, aval}
__device__ int2   g_cr[EHALF];      // user-side CSR slots: {col, reverse slot}
__device__ int    g_off[EMAX];      // per-edge within-row offset (from hist atomics)
__device__ int    g_rowptr[NN + 1];
__device__ int    g_deg[NN];
__device__ int    g_bsum[128];      // published block totals + 1 (0 = unpublished)
__device__ float  g_U[2048 * D];    // 0.25*(emb0+..+emb3) at sampled user rows
__device__ float  g_I[2048 * D];    // same for items

// ---------------- fused: degree histogram (+offset capture) + emb init + rnorm0 ----

__global__ __launch_bounds__(256) void k_hist_init(const int* __restrict__ src, int E,
                                                   const float* __restrict__ ue,
                                                   const float* __restrict__ ie) {
    if (blockIdx.x < INIT_BLKS) {
        int row = blockIdx.x * 8 + (threadIdx.x >> 5);
        if (row >= NN) return;
        int lane = threadIdx.x & 31;
        const float* srcp = (row < N_USER) ? (ue + row * D) : (ie + (row - N_USER) * D);
        float2 v = *(const float2*)(srcp + lane * 2);
        *(float2*)(g_embA + row * D + lane * 2) = v;
        float s = v.x * v.x + v.y * v.y;
        #pragma unroll
        for (int o = 16; o; o >>= 1) s += __shfl_xor_sync(0xffffffffu, s, o);
        if (lane == 0) g_rnorm[row] = (s > 1e-24f) ? rsqrtf(s) : 0.f;
    } else {
        // histogram that also records each edge's within-row slot offset
        int base = (blockIdx.x - INIT_BLKS) * 256 + threadIdx.x;
        for (int e = base; e < E; e += HIST_BLKS * 256)
            g_off[e] = atomicAdd(&g_deg[src[e]], 1);
    }
}

// ---------------- CSR build: single-kernel scan (decoupled aggregate lookback) ----

__global__ __launch_bounds__(1024) void k_scan(int E) {
    __shared__ int wsum[32];
    __shared__ int pred[128];
    int i = blockIdx.x * 1024 + threadIdx.x;
    int lane = threadIdx.x & 31, wid = threadIdx.x >> 5;
    int v = (i < NN) ? g_deg[i] : 0;
    int x = v;
    #pragma unroll
    for (int o = 1; o < 32; o <<= 1) {
        int y = __shfl_up_sync(0xffffffffu, x, o);
        if (lane >= o) x += y;
    }
    if (lane == 31) wsum[wid] = x;
    __syncthreads();
    if (wid == 0) {
        int s = wsum[lane];
        #pragma unroll
        for (int o = 1; o < 32; o <<= 1) {
            int y = __shfl_up_sync(0xffffffffu, s, o);
            if (lane >= o) s += y;
        }
        wsum[lane] = s;
    }
    __syncthreads();
    int woff = (wid > 0) ? wsum[wid - 1] : 0;
    int incl = x + woff;            // block-local inclusive prefix
    int excl = incl - v;            // block-local exclusive prefix

    // publish this block's total (encoded +1; 0 means unpublished)
    if (threadIdx.x == 1023)
        atomicExch(&g_bsum[blockIdx.x], incl + 1);

    // gather predecessor aggregates (all 98 blocks are wave-1 resident)
    int t = threadIdx.x;
    if (t < 128) {
        int val = 0;
        if (t < blockIdx.x) {
            int p;
            do { p = *(volatile int*)&g_bsum[t]; } while (p == 0);
            val = p - 1;
        }
        pred[t] = val;
    }
    __syncthreads();
    if (t < 64) pred[t] += pred[t + 64];
    __syncthreads();
    if (t < 32) {
        int s = pred[t] + pred[t + 32];
        #pragma unroll
        for (int o = 16; o; o >>= 1) s += __shfl_down_sync(0xffffffffu, s, o);
        if (t == 0) pred[0] = s;
    }
    __syncthreads();
    int off = pred[0];
    if (i < NN) g_rowptr[i] = excl + off;
    if (i == 0) g_rowptr[NN] = E;
}

// atomic-free scatter: slot = rowptr[node] + precomputed offset
__global__ __launch_bounds__(1024) void k_scatter(const int* __restrict__ src,
                                                  const float* __restrict__ adj,
                                                  int EH) {
    int e = blockIdx.x * 1024 + threadIdx.x;
    if (e >= EH) return;
    int u  = src[e];
    int iv = src[e + EH];
    float a = adj[e];
    int pos1 = g_rowptr[u]  + g_off[e];
    int pos2 = g_rowptr[iv] + g_off[e + EH];
    g_edge[pos1] = make_float4(__int_as_float(iv), 0.f, a, a);
    g_edge[pos2] = make_float4(__int_as_float(u), 0.f, a, a);
    g_cr[pos1]   = make_int2(iv, pos2);   // user rows occupy slots [0, EH)
}

// ---------------- per-layer edge passes (verified R13 bodies) ----------------

__global__ __launch_bounds__(256) void k_cos(int cur) {
    const float* __restrict__ emb = cur ? g_embB : g_embA;
    int row = blockIdx.x * 8 + (threadIdx.x >> 5);
    if (row >= N_USER) return;
    int lane = threadIdx.x & 31;
    int g = lane >> 3, sl = lane & 7;

    const float* rp = emb + row * D + sl * 4;
    float4 e0 = *(const float4*)(rp);
    float4 e1 = *(const float4*)(rp + 32);
    float rn_r = g_rnorm[row];

    int beg = g_rowptr[row], end = g_rowptr[row + 1];
    int nit = (end - beg + 3) >> 2;

    int pos = beg + g;
    bool actn = pos < end;
    int2 crn = actn ? g_cr[pos] : make_int2(0, 0);

    float rs = 0.f;
    for (int it = 0; it < nit; it++) {
        bool act = actn;
        int2 cr = crn;
        int curpos = pos;
        pos += 4;
        actn = pos < end;
        if (actn) crn = g_cr[pos];

        float p = 0.f;
        float rn_c = 0.f;
        if (act) {
            const float* cp = emb + cr.x * D + sl * 4;
            float4 d0 = *(const float4*)(cp);
            float4 d1 = *(const float4*)(cp + 32);
            rn_c = g_rnorm[cr.x];
            p = e0.x * d0.x + e0.y * d0.y + e0.z * d0.z + e0.w * d0.w
              + e1.x * d1.x + e1.y * d1.y + e1.z * d1.z + e1.w * d1.w;
        }
        p += __shfl_xor_sync(0xffffffffu, p, 1);
        p += __shfl_xor_sync(0xffffffffu, p, 2);
        p += __shfl_xor_sync(0xffffffffu, p, 4);
        float cs = p * rn_r * rn_c;
        if (act && sl == 0) {
            ((float*)(g_edge + curpos))[1] = cs;   // user-side slot
            ((float*)(g_edge + cr.y))[1]   = cs;   // item-side (reverse) slot
            atomicAdd(&g_rowacc[cr.x - N_USER], fabsf(cs));  // item L1 rowsum
        }
        rs += fabsf(cs);
    }
    rs += __shfl_xor_sync(0xffffffffu, rs, 8);
    rs += __shfl_xor_sync(0xffffffffu, rs, 16);
    if (lane == 0) g_rowsum[row] = (rs > 0.f) ? 1.f / rs : 1.f;
}

// invert the atomically-accumulated item rowsums; reset accumulators for next layer
__global__ void k_rsinv_it() {
    int i = blockIdx.x * blockDim.x + threadIdx.x;
    if (i < N_ITEM) {
        float rs = g_rowacc[i];
        g_rowsum[N_USER + i] = (rs > 0.f) ? 1.f / rs : 1.f;
        g_rowacc[i] = 0.f;
    }
}

// layers 0,1 only: coef -> prune -> mem EMA -> SpMM row accumulate (+ next rnorm)
__global__ __launch_bounds__(256) void k_spmm(int cur,
                                              const float* __restrict__ W,
                                              const float* __restrict__ B) {
    const float* __restrict__ embin = cur ? g_embB : g_embA;
    float* embout                   = cur ? g_embA : g_embB;
    int row = blockIdx.x * 8 + (threadIdx.x >> 5);
    if (row >= NN) return;
    int lane = threadIdx.x & 31;
    int g = lane >> 3, sl = lane & 7;

    float w0 = W[0], w1 = W[1], bb = B[0];
    float invr = g_rowsum[row];
    int beg = g_rowptr[row], end = g_rowptr[row + 1];
    int nit = (end - beg + 3) >> 2;

    int pos = beg + g;
    bool actn = pos < end;
    float4 en = actn ? g_edge[pos] : make_float4(0, 0, 0, 0);

    float a0 = 0.f, a1 = 0.f, a2 = 0.f, a3 = 0.f;
    float a4 = 0.f, a5 = 0.f, a6 = 0.f, a7 = 0.f;
    for (int it = 0; it < nit; it++) {
        bool act = actn;
        float4 er = en;
        int curpos = pos;
        pos += 4;
        actn = pos < end;
        if (actn) en = g_edge[pos];

        if (act) {
            int c = __float_as_int(er.x);
            float cs = er.y;
            float c1 = cs * invr;
            float c2 = cs * g_rowsum[c];           // cos symmetric
            float z = w0 * c1 + w1 * c2 + bb;      // sigmoid(z)>0.5 <=> z>0
            float coef = (z > 0.f) ? c1 : 0.f;
            float m = 0.5f * (er.z + coef);
            if (sl == 0) ((float*)(g_edge + curpos))[2] = m;
            float gv = m * er.w;
            const float* cp = embin + c * D + sl * 4;
            float4 d0 = *(const float4*)(cp);
            float4 d1 = *(const float4*)(cp + 32);
            a0 += gv * d0.x; a1 += gv * d0.y; a2 += gv * d0.z; a3 += gv * d0.w;
            a4 += gv * d1.x; a5 += gv * d1.y; a6 += gv * d1.z; a7 += gv * d1.w;
        }
    }
    #pragma unroll
    for (int o = 8; o <= 16; o <<= 1) {
        a0 += __shfl_xor_sync(0xffffffffu, a0, o);
        a1 += __shfl_xor_sync(0xffffffffu, a1, o);
        a2 += __shfl_xor_sync(0xffffffffu, a2, o);
        a3 += __shfl_xor_sync(0xffffffffu, a3, o);
        a4 += __shfl_xor_sync(0xffffffffu, a4, o);
        a5 += __shfl_xor_sync(0xffffffffu, a5, o);
        a6 += __shfl_xor_sync(0xffffffffu, a6, o);
        a7 += __shfl_xor_sync(0xffffffffu, a7, o);
    }
    float ss = a0 * a0 + a1 * a1 + a2 * a2 + a3 * a3
             + a4 * a4 + a5 * a5 + a6 * a6 + a7 * a7;
    ss += __shfl_xor_sync(0xffffffffu, ss, 1);
    ss += __shfl_xor_sync(0xffffffffu, ss, 2);
    ss += __shfl_xor_sync(0xffffffffu, ss, 4);
    if (g == 0) {
        float* op = embout + row * D + sl * 4;
        *(float4*)(op)      = make_float4(a0, a1, a2, a3);
        *(float4*)(op + 32) = make_float4(a4, a5, a6, a7);
        if (sl == 0) g_rnorm[row] = (ss > 1e-24f) ? rsqrtf(ss) : 0.f;
    }
}

// layer-2 SpMM restricted to the SAMPLED rows only, fused with the light mean
__global__ __launch_bounds__(256) void k_final(const int* __restrict__ users,
                                               const int* __restrict__ items,
                                               const float* __restrict__ ue,
                                               const float* __restrict__ ie,
                                               const float* __restrict__ W,
                                               const float* __restrict__ B,
                                               int Bu, int Bi) {
    int idx = blockIdx.x * 8 + (threadIdx.x >> 5);   // sample index
    if (idx >= Bu + Bi) return;
    int lane = threadIdx.x & 31;
    int g = lane >> 3, sl = lane & 7;

    bool isU = idx < Bu;
    int row = isU ? users[idx] : (N_USER + items[idx - Bu]);
    float* outp = isU ? (g_U + idx * D) : (g_I + (idx - Bu) * D);
    const float* e0p = isU ? (ue + row * D) : (ie + (row - N_USER) * D);

    const float* __restrict__ embin = g_embA;   // emb2 (layer-1 output)

    float w0 = W[0], w1 = W[1], bb = B[0];
    float invr = g_rowsum[row];
    int beg = g_rowptr[row], end = g_rowptr[row + 1];
    int nit = (end - beg + 3) >> 2;

    int pos = beg + g;
    bool actn = pos < end;
    float4 en = actn ? g_edge[pos] : make_float4(0, 0, 0, 0);

    float a0 = 0.f, a1 = 0.f, a2 = 0.f, a3 = 0.f;
    float a4 = 0.f, a5 = 0.f, a6 = 0.f, a7 = 0.f;
    for (int it = 0; it < nit; it++) {
        bool act = actn;
        float4 er = en;
        pos += 4;
        actn = pos < end;
        if (actn) en = g_edge[pos];

        if (act) {
            int c = __float_as_int(er.x);
            float cs = er.y;
            float c1 = cs * invr;
            float c2 = cs * g_rowsum[c];
            float z = w0 * c1 + w1 * c2 + bb;
            float coef = (z > 0.f) ? c1 : 0.f;
            float m = 0.5f * (er.z + coef);      // no mem writeback (last layer)
            float gv = m * er.w;
            const float* cp = embin + c * D + sl * 4;
            float4 d0 = *(const float4*)(cp);
            float4 d1 = *(const float4*)(cp + 32);
            a0 += gv * d0.x; a1 += gv * d0.y; a2 += gv * d0.z; a3 += gv * d0.w;
            a4 += gv * d1.x; a5 += gv * d1.y; a6 += gv * d1.z; a7 += gv * d1.w;
        }
    }
    #pragma unroll
    for (int o = 8; o <= 16; o <<= 1) {
        a0 += __shfl_xor_sync(0xffffffffu, a0, o);
        a1 += __shfl_xor_sync(0xffffffffu, a1, o);
        a2 += __shfl_xor_sync(0xffffffffu, a2, o);
        a3 += __shfl_xor_sync(0xffffffffu, a3, o);
        a4 += __shfl_xor_sync(0xffffffffu, a4, o);
        a5 += __shfl_xor_sync(0xffffffffu, a5, o);
        a6 += __shfl_xor_sync(0xffffffffu, a6, o);
        a7 += __shfl_xor_sync(0xffffffffu, a7, o);
    }
    if (g == 0) {
        float4 z0 = *(const float4*)(e0p + sl * 4);           // emb0 (inputs)
        float4 z1 = *(const float4*)(e0p + sl * 4 + 32);
        const float* b1 = g_embB + row * D + sl * 4;          // emb1
        float4 y0 = *(const float4*)(b1);
        float4 y1 = *(const float4*)(b1 + 32);
        const float* b2 = g_embA + row * D + sl * 4;          // emb2
        float4 x0 = *(const float4*)(b2);
        float4 x1 = *(const float4*)(b2 + 32);
        float4 r0 = make_float4(0.25f * (z0.x + y0.x + x0.x + a0),
                                0.25f * (z0.y + y0.y + x0.y + a1),
                                0.25f * (z0.z + y0.z + x0.z + a2),
                                0.25f * (z0.w + y0.w + x0.w + a3));
        float4 r1 = make_float4(0.25f * (z1.x + y1.x + x1.x + a4),
                                0.25f * (z1.y + y1.y + x1.y + a5),
                                0.25f * (z1.z + y1.z + x1.z + a6),
                                0.25f * (z1.w + y1.w + x1.w + a7));
        *(float4*)(outp + sl * 4)      = r0;
        *(float4*)(outp + sl * 4 + 32) = r1;
    }
}

// ---------------- final sigmoid GEMM (verified R13 version; FMA-bound) ----------

__global__ void k_gemm(float* __restrict__ out, int Bu, int Bi) {
    __shared__ float As[64][65];
    __shared__ float Bs[64][65];
    int tx = threadIdx.x, ty = threadIdx.y;       // 16x16
    int t = ty * 16 + tx;
    int rowBase = blockIdx.y * 64, colBase = blockIdx.x * 64;
    #pragma unroll
    for (int i = 0; i < 4; i++) {
        int j = t + i * 256;       // float4 slot 0..1023
        int r = j >> 4;
        int kq = (j & 15) * 4;
        float4 a = (rowBase + r < Bu) ? *(const float4*)(g_U + (rowBase + r) * 64 + kq)
                                      : make_float4(0, 0, 0, 0);
        As[r][kq] = a.x; As[r][kq + 1] = a.y; As[r][kq + 2] = a.z; As[r][kq + 3] = a.w;
        float4 b = (colBase + r < Bi) ? *(const float4*)(g_I + (colBase + r) * 64 + kq)
                                      : make_float4(0, 0, 0, 0);
        Bs[r][kq] = b.x; Bs[r][kq + 1] = b.y; Bs[r][kq + 2] = b.z; Bs[r][kq + 3] = b.w;
    }
    __syncthreads();
    float acc[4][4] = {};
    #pragma unroll
    for (int k = 0; k < 64; k++) {
        float a0 = As[ty * 4 + 0][k], a1 = As[ty * 4 + 1][k];
        float a2 = As[ty * 4 + 2][k], a3 = As[ty * 4 + 3][k];
        float b0 = Bs[tx * 4 + 0][k], b1 = Bs[tx * 4 + 1][k];
        float b2 = Bs[tx * 4 + 2][k], b3 = Bs[tx * 4 + 3][k];
        acc[0][0] += a0 * b0; acc[0][1] += a0 * b1; acc[0][2] += a0 * b2; acc[0][3] += a0 * b3;
        acc[1][0] += a1 * b0; acc[1][1] += a1 * b1; acc[1][2] += a1 * b2; acc[1][3] += a1 * b3;
        acc[2][0] += a2 * b0; acc[2][1] += a2 * b1; acc[2][2] += a2 * b2; acc[2][3] += a2 * b3;
        acc[3][0] += a3 * b0; acc[3][1] += a3 * b1; acc[3][2] += a3 * b2; acc[3][3] += a3 * b3;
    }
    #pragma unroll
    for (int i = 0; i < 4; i++)
        #pragma unroll
        for (int j = 0; j < 4; j++) {
            int r = rowBase + ty * 4 + i;
            int c = colBase + tx * 4 + j;
            if (r < Bu && c < Bi)
                out[r * Bi + c] = 1.f / (1.f + __expf(-acc[i][j]));
        }
}

// ---------------- launch ----------------

extern "C" void kernel_launch(void* const* d_in, const int* in_sizes, int n_in,
                              void* d_out, int out_size) {
    const int*   users    = (const int*)d_in[0];
    const int*   items    = (const int*)d_in[1];
    const float* user_emb = (const float*)d_in[2];
    const float* item_emb = (const float*)d_in[3];
    const float* W_prune  = (const float*)d_in[4];
    const float* b_prune  = (const float*)d_in[5];
    const int*   src      = (const int*)d_in[6];
    // d_in[7] = dst (mirrors src), d_in[8] = rev_perm (unused)
    const float* adj_vals = (const float*)d_in[9];

    int Bu = in_sizes[0];
    int Bi = in_sizes[1];
    int E  = in_sizes[6];
    int EH = E / 2;

    float* out = (float*)d_out;

    // zero degree counters, item rowsum accumulators, scan publish slots
    void* degp = nullptr;
    cudaGetSymbolAddress(&degp, g_deg);
    cudaMemsetAsync(degp, 0, NN * sizeof(int));
    void* accp = nullptr;
    cudaGetSymbolAddress(&accp, g_rowacc);
    cudaMemsetAsync(accp, 0, N_ITEM * sizeof(float));
    void* bsump = nullptr;
    cudaGetSymbolAddress(&bsump, g_bsum);
    cudaMemsetAsync(bsump, 0, 128 * sizeof(int));

    // fused: degree histogram (capturing per-edge offsets) + emb init + rnorm0
    k_hist_init<<<INIT_BLKS + HIST_BLKS, 256>>>(src, E, user_emb, item_emb);

    // CSR build: single-kernel decoupled-lookback scan, then atomic-free scatter
    k_scan<<<NB_SCAN, 1024>>>(E);
    k_scatter<<<(EH + 1023) / 1024, 1024>>>(src, adj_vals, EH);

    // layers 0,1: full passes
    int ublocks = (N_USER + 7) / 8;
    int ablocks = (NN + 7) / 8;
    int riblocks = (N_ITEM + 1023) / 1024;
    for (int l = 0; l < 2; l++) {
        k_cos<<<ublocks, 256>>>(l & 1);
        k_rsinv_it<<<riblocks, 1024>>>();
        k_spmm<<<ablocks, 256>>>(l & 1, W_prune, b_prune);
    }
    // layer 2: full cos + rowsum, then SpMM only at the 4096 sampled rows
    k_cos<<<ublocks, 256>>>(0);          // emb2 in g_embA
    k_rsinv_it<<<riblocks, 1024>>>();
    int fblocks = (Bu + Bi + 7) / 8;
    k_final<<<fblocks, 256>>>(users, items, user_emb, item_emb,
                              W_prune, b_prune, Bu, Bi);

    // sigmoid GEMM on the pre-scaled sampled embeddings
    dim3 gblk(16, 16);
    dim3 ggrd((Bi + 63) / 64, (Bu + 63) / 64);
    k_gemm<<<ggrd, gblk>>>(out, Bu, Bi);
}